// round 1
// baseline (speedup 1.0000x reference)
#include <cuda_runtime.h>

#define PI_F 3.14159265358979323846f

static __device__ __forceinline__ int padi(int i){ return i + (i>>5); }

static __device__ __forceinline__ void cmul(float ar,float ai,float br,float bi,float&cr,float&ci){
  cr = ar*br - ai*bi; ci = ar*bi + ai*br;
}

// DFT-8 (unscaled, e^{-2pi i mq/8}) on 8 complex values in registers.
static __device__ __forceinline__ void dft8(float xr[8], float xi[8]) {
  const float C = 0.70710678118654752440f;
  float u0r=xr[0]+xr[4], u0i=xi[0]+xi[4];
  float u1r=xr[0]-xr[4], u1i=xi[0]-xi[4];
  float u2r=xr[2]+xr[6], u2i=xi[2]+xi[6];
  float u3r=xr[2]-xr[6], u3i=xi[2]-xi[6];
  float E0r=u0r+u2r, E0i=u0i+u2i;
  float E1r=u1r+u3i, E1i=u1i-u3r;
  float E2r=u0r-u2r, E2i=u0i-u2i;
  float E3r=u1r-u3i, E3i=u1i+u3r;
  float v0r=xr[1]+xr[5], v0i=xi[1]+xi[5];
  float v1r=xr[1]-xr[5], v1i=xi[1]-xi[5];
  float v2r=xr[3]+xr[7], v2i=xi[3]+xi[7];
  float v3r=xr[3]-xr[7], v3i=xi[3]-xi[7];
  float O0r=v0r+v2r, O0i=v0i+v2i;
  float O1r=v1r+v3i, O1i=v1i-v3r;
  float O2r=v0r-v2r, O2i=v0i-v2i;
  float O3r=v1r-v3i, O3i=v1i+v3r;
  float w1r=C*(O1r+O1i), w1i=C*(O1i-O1r);
  float w2r=O2i,          w2i=-O2r;
  float w3r=C*(O3i-O3r),  w3i=-C*(O3r+O3i);
  xr[0]=E0r+O0r; xi[0]=E0i+O0i;
  xr[4]=E0r-O0r; xi[4]=E0i-O0i;
  xr[1]=E1r+w1r; xi[1]=E1i+w1i;
  xr[5]=E1r-w1r; xi[5]=E1i-w1i;
  xr[2]=E2r+w2r; xi[2]=E2i+w2i;
  xr[6]=E2r-w2r; xi[6]=E2i-w2i;
  xr[3]=E3r+w3r; xi[3]=E3i+w3i;
  xr[7]=E3r-w3r; xi[7]=E3i-w3i;
}

// Block sum: result valid on thread 0 only. 256 threads, all must call.
static __device__ float block_sum(float v, float* scr){
  #pragma unroll
  for (int o=16;o;o>>=1) v += __shfl_xor_sync(0xffffffffu, v, o);
  __syncthreads();
  if ((threadIdx.x&31)==0) scr[threadIdx.x>>5] = v;
  __syncthreads();
  float r = 0.f;
  if (threadIdx.x==0){ for (int i=0;i<8;i++) r += scr[i]; }
  return r;
}
static __device__ float block_max(float v, float* scr){
  #pragma unroll
  for (int o=16;o;o>>=1) v = fmaxf(v, __shfl_xor_sync(0xffffffffu, v, o));
  __syncthreads();
  if ((threadIdx.x&31)==0) scr[threadIdx.x>>5] = v;
  __syncthreads();
  float r = -3.0e38f;
  if (threadIdx.x==0){ for (int i=0;i<8;i++) r = fmaxf(r, scr[i]); }
  return r;
}
static __device__ float block_min(float v, float* scr){
  #pragma unroll
  for (int o=16;o;o>>=1) v = fminf(v, __shfl_xor_sync(0xffffffffu, v, o));
  __syncthreads();
  if ((threadIdx.x&31)==0) scr[threadIdx.x>>5] = v;
  __syncthreads();
  float r = 3.0e38f;
  if (threadIdx.x==0){ for (int i=0;i<8;i++) r = fminf(r, scr[i]); }
  return r;
}

__global__ void __launch_bounds__(256)
feat_kernel(const float* __restrict__ x, float* __restrict__ out)
{
  __shared__ float s_sig[2048];
  __shared__ float s_re[2112];   // 2048 + 2048/32 pad
  __shared__ float s_im[2112];
  __shared__ float scr[8];
  __shared__ int sh_np, sh_nv, sh_p0, sh_v0, sh_vl, sh_v1, sh_li, sh_ri;

  const int tid = threadIdx.x;
  const size_t row = blockIdx.x;
  const float* xp = x + row * 2048;

  // ---- load row into smem (coalesced float4) ----
  {
    const float4* xv = (const float4*)xp;
    float4* sv = (float4*)s_sig;
    sv[tid]       = xv[tid];
    sv[tid + 256] = xv[tid + 256];
  }
  if (tid==0){
    sh_np=0; sh_nv=0; sh_p0=0x7fffffff; sh_v0=0x7fffffff;
    sh_vl=-1; sh_v1=0x7fffffff; sh_li=0x7fffffff; sh_ri=-1;
  }
  __syncthreads();

  // ================= FFT: DIF radix 8,8,8,4 — no bit-reversal needed =================
  float ar[8], ai[8];
  float mx=-3.0e38f, mn=3.0e38f, sm=0.f, sq=0.f;

  // ---- pass 1: L=2048, r=8, t = tid (real inputs -> im folds to 0) ----
  #pragma unroll
  for (int m=0;m<8;m++){
    float v = s_sig[tid + 256*m];
    ar[m]=v; ai[m]=0.f;
    mx=fmaxf(mx,v); mn=fminf(mn,v); sm+=v; sq+=v*v;
  }
  dft8(ar, ai);
  {
    float sn,cs; __sincosf(-2.f*PI_F*(float)tid*(1.f/2048.f), &sn, &cs);
    float wr=cs, wi=sn;
    { int o=padi(tid); s_re[o]=ar[0]; s_im[o]=ai[0]; }
    #pragma unroll
    for (int q=1;q<8;q++){
      float rr,ii; cmul(ar[q],ai[q],wr,wi,rr,ii);
      int o=padi(tid + q*256); s_re[o]=rr; s_im[o]=ii;
      float nr,ni; cmul(wr,wi,cs,sn,nr,ni); wr=nr; wi=ni;
    }
  }
  __syncthreads();

  // ---- pass 2: L=256, r=8; sub = tid>>5 (warp), t = lane ----
  {
    int sub = tid>>5, t = tid&31, base = sub<<8;
    #pragma unroll
    for (int m=0;m<8;m++){ int o=padi(base + t + (m<<5)); ar[m]=s_re[o]; ai[m]=s_im[o]; }
    __syncthreads();
    dft8(ar, ai);
    float sn,cs; __sincosf(-2.f*PI_F*(float)t*(1.f/256.f), &sn, &cs);
    float wr=cs, wi=sn;
    { int o=padi(base + t); s_re[o]=ar[0]; s_im[o]=ai[0]; }
    #pragma unroll
    for (int q=1;q<8;q++){
      float rr,ii; cmul(ar[q],ai[q],wr,wi,rr,ii);
      int o=padi(base + t + (q<<5)); s_re[o]=rr; s_im[o]=ii;
      float nr,ni; cmul(wr,wi,cs,sn,nr,ni); wr=nr; wi=ni;
    }
  }
  __syncthreads();

  // ---- pass 3: L=32, r=8; t = tid>>6 (0..3), sid = tid&63 -> conflict-free banks ----
  {
    int t = tid>>6, sid = tid&63, base = sid<<5;
    #pragma unroll
    for (int m=0;m<8;m++){ int o=padi(base + t + (m<<2)); ar[m]=s_re[o]; ai[m]=s_im[o]; }
    __syncthreads();
    dft8(ar, ai);
    float sn,cs; __sincosf(-2.f*PI_F*(float)t*(1.f/32.f), &sn, &cs);
    float wr=cs, wi=sn;
    { int o=padi(base + t); s_re[o]=ar[0]; s_im[o]=ai[0]; }
    #pragma unroll
    for (int q=1;q<8;q++){
      float rr,ii; cmul(ar[q],ai[q],wr,wi,rr,ii);
      int o=padi(base + t + (q<<2)); s_re[o]=rr; s_im[o]=ii;
      float nr,ni; cmul(wr,wi,cs,sn,nr,ni); wr=nr; wi=ni;
    }
  }
  __syncthreads();

  // ---- pass 4: L=4, r=4, t=0 (no twiddle); accumulate |X| directly ----
  float mag = 0.f;
  #pragma unroll
  for (int h=0; h<2; h++){
    int b = (tid + (h<<8))<<2;
    float r0=s_re[padi(b+0)], i0=s_im[padi(b+0)];
    float r1=s_re[padi(b+1)], i1=s_im[padi(b+1)];
    float r2=s_re[padi(b+2)], i2=s_im[padi(b+2)];
    float r3=s_re[padi(b+3)], i3=s_im[padi(b+3)];
    float u0r=r0+r2, u0i=i0+i2, u1r=r0-r2, u1i=i0-i2;
    float u2r=r1+r3, u2i=i1+i3, u3r=r1-r3, u3i=i1-i3;
    float y0r=u0r+u2r, y0i=u0i+u2i;
    float y2r=u0r-u2r, y2i=u0i-u2i;
    float y1r=u1r+u3i, y1i=u1i-u3r;
    float y3r=u1r-u3i, y3i=u1i+u3r;
    mag += sqrtf(y0r*y0r+y0i*y0i) + sqrtf(y1r*y1r+y1i*y1i)
         + sqrtf(y2r*y2r+y2i*y2i) + sqrtf(y3r*y3r+y3i*y3i);
  }

  // ---- deterministic float reductions (valid on tid 0) ----
  float sm_t  = block_sum(sm,  scr);
  float sq_t  = block_sum(sq,  scr);
  float mag_t = block_sum(mag, scr);
  float mx_t  = block_max(mx,  scr);
  float mn_t  = block_min(mn,  scr);

  // ================= peak/valley features =================
  // Cache s[i-1], s[i], s[i+1] for i = 1 + tid + 256*r (strided, conflict-free)
  float sl[8], sc[8], srr[8];
  #pragma unroll
  for (int r=0;r<8;r++){
    sl[r]=0.f; sc[r]=0.f; srr[r]=0.f;
    int i = 1 + tid + (r<<8);
    if (i<=2047){ sl[r]=s_sig[i-1]; sc[r]=s_sig[i]; }
    if (i<=2046){ srr[r]=s_sig[i+1]; }
  }

  // Phase 1: counts, first peak, first/last valley
  {
    int lnp=0, lnv=0, lp0=0x7fffffff, lv0=0x7fffffff, lvl=-1;
    #pragma unroll
    for (int r=0;r<8;r++){
      int i = 1 + tid + (r<<8);
      if (i<=2046){
        bool pk = (sl[r]<sc[r]) && (sc[r]>srr[r]);
        bool vl = (sl[r]>sc[r]) && (sc[r]<srr[r]);
        if (pk){ lnp++; lp0 = min(lp0,i); }
        if (vl){ lnv++; lv0 = min(lv0,i); lvl = max(lvl,i); }
      }
    }
    if (lnp) atomicAdd(&sh_np, lnp);
    if (lnv) atomicAdd(&sh_nv, lnv);
    if (lp0!=0x7fffffff) atomicMin(&sh_p0, lp0);
    if (lv0!=0x7fffffff){ atomicMin(&sh_v0, lv0); atomicMax(&sh_vl, lvl); }
  }
  __syncthreads();

  const int np = sh_np, nv = sh_nv;
  const int p0 = (sh_p0==0x7fffffff) ? 1 : sh_p0;
  const int v0 = (sh_v0==0x7fffffff) ? 1 : sh_v0;
  const int vlast = (sh_vl<0) ? 2046 : sh_vl;
  const float half = 0.5f*(s_sig[p0] + s_sig[v0]);

  // Phase 2: second valley (>v0), half-height crossings
  {
    int lv1=0x7fffffff, lli=0x7fffffff, lri=-1;
    #pragma unroll
    for (int r=0;r<8;r++){
      int i = 1 + tid + (r<<8);
      if (i<=2046){
        bool vl = (sl[r]>sc[r]) && (sc[r]<srr[r]);
        if (vl && i>v0) lv1 = min(lv1,i);
        float sv = sc[r];
        if (sv>=half){
          if (i>=v0 && i< p0) lli = min(lli,i);
          if (i> v0 && i<=p0) lri = max(lri,i);
        }
      }
    }
    if (lv1!=0x7fffffff) atomicMin(&sh_v1, lv1);
    if (lli!=0x7fffffff) atomicMin(&sh_li, lli);
    if (lri>=0)          atomicMax(&sh_ri, lri);
  }
  __syncthreads();

  const int v1 = (sh_v1==0x7fffffff) ? 1  : sh_v1;
  const int li = (sh_li==0x7fffffff) ? v0 : sh_li;
  const int ri = (sh_ri<0)           ? p0 : sh_ri;

  // Phase 3: masked trapezoid sums (pair index ip: pairs[ip]=0.5*(s[ip]+s[ip+1]))
  float aPA=0.f, aA2=0.f, aA1=0.f;
  #pragma unroll
  for (int r=0;r<8;r++){
    int ip = tid + (r<<8);
    if (ip<=2046){
      float pr = 0.5f*(sl[r] + sc[r]);   // sl=s[ip], sc=s[ip+1]
      if (ip>=v0 && ip<=vlast-2) aPA += pr;
      if (ip>=p0 && ip<=v1-2)    aA2 += pr;
      if (ip>=v0 && ip<=p0-2)    aA1 += pr;
    }
  }
  float PA_t = block_sum(aPA, scr);
  float A2_t = block_sum(aA2, scr);
  float A1_t = block_sum(aA1, scr);

  // ---- write 10 features ----
  if (tid==0){
    const float n = 2048.f;
    float var = (sq_t - sm_t*sm_t/n) / (n - 1.f);
    var = fmaxf(var, 0.f);
    float stdv = sqrtf(var);
    float mean_amp = mag_t / n;
    bool gate = (np>=1) && (nv>=2);
    float PA=0.f, A2=0.f, PH=0.f, A1=0.f, PW=0.f;
    if (gate){
      PA = PA_t / 30.0f;
      A2 = A2_t / 30.0f;
      A1 = A1_t / 30.0f;
      PH = s_sig[p0] - s_sig[v0];
      PW = (float)(ri - li) / 30.0f;
    }
    float* o = out + row*10;
    o[0]=mx_t; o[1]=mx_t-mn_t; o[2]=var; o[3]=stdv; o[4]=mean_amp;
    o[5]=PA;   o[6]=A2;        o[7]=PH;  o[8]=A1;   o[9]=PW;
  }
}

extern "C" void kernel_launch(void* const* d_in, const int* in_sizes, int n_in,
                              void* d_out, int out_size) {
  const float* x = (const float*)d_in[0];
  float* out = (float*)d_out;
  (void)in_sizes; (void)n_in; (void)out_size;
  feat_kernel<<<32768, 256>>>(x, out);
}

// round 2
// speedup vs baseline: 1.1522x; 1.1522x over previous
#include <cuda_runtime.h>

#define PI_F 3.14159265358979323846f

static __device__ __forceinline__ void cmul(float ar,float ai,float br,float bi,float&cr,float&ci){
  cr = ar*br - ai*bi; ci = ar*bi + ai*br;
}

// DFT-8 (unscaled, e^{-2pi i mq/8}) on 8 complex values in registers.
static __device__ __forceinline__ void dft8(float xr[8], float xi[8]) {
  const float C = 0.70710678118654752440f;
  float u0r=xr[0]+xr[4], u0i=xi[0]+xi[4];
  float u1r=xr[0]-xr[4], u1i=xi[0]-xi[4];
  float u2r=xr[2]+xr[6], u2i=xi[2]+xi[6];
  float u3r=xr[2]-xr[6], u3i=xi[2]-xi[6];
  float E0r=u0r+u2r, E0i=u0i+u2i;
  float E1r=u1r+u3i, E1i=u1i-u3r;
  float E2r=u0r-u2r, E2i=u0i-u2i;
  float E3r=u1r-u3i, E3i=u1i+u3r;
  float v0r=xr[1]+xr[5], v0i=xi[1]+xi[5];
  float v1r=xr[1]-xr[5], v1i=xi[1]-xi[5];
  float v2r=xr[3]+xr[7], v2i=xi[3]+xi[7];
  float v3r=xr[3]-xr[7], v3i=xi[3]-xi[7];
  float O0r=v0r+v2r, O0i=v0i+v2i;
  float O1r=v1r+v3i, O1i=v1i-v3r;
  float O2r=v0r-v2r, O2i=v0i-v2i;
  float O3r=v1r-v3i, O3i=v1i+v3r;
  float w1r=C*(O1r+O1i), w1i=C*(O1i-O1r);
  float w2r=O2i,          w2i=-O2r;
  float w3r=C*(O3i-O3r),  w3i=-C*(O3r+O3i);
  xr[0]=E0r+O0r; xi[0]=E0i+O0i;
  xr[4]=E0r-O0r; xi[4]=E0i-O0i;
  xr[1]=E1r+w1r; xi[1]=E1i+w1i;
  xr[5]=E1r-w1r; xi[5]=E1i-w1i;
  xr[2]=E2r+w2r; xi[2]=E2i+w2i;
  xr[6]=E2r-w2r; xi[6]=E2i-w2i;
  xr[3]=E3r+w3r; xi[3]=E3i+w3i;
  xr[7]=E3r-w3r; xi[7]=E3i-w3i;
}

__global__ void __launch_bounds__(256)
feat_kernel(const float* __restrict__ x, float* __restrict__ out)
{
  __shared__ float  s_sig[2048];
  __shared__ float2 s_d[2112];     // 2048 + 64 pad (index i -> i + (i>>5))
  __shared__ float  scr[40];
  __shared__ int sh_np, sh_nv, sh_p0, sh_v0, sh_vl, sh_v1, sh_li, sh_ri;

  const int tid  = threadIdx.x;
  const int lane = tid & 31;
  const int warp = tid >> 5;
  const size_t row = blockIdx.x;
  const float* xp = x + row * 2048;

  // ---- load row into smem (coalesced float4) ----
  {
    const float4* xv = (const float4*)xp;
    float4* sv = (float4*)s_sig;
    sv[tid]       = xv[tid];
    sv[tid + 256] = xv[tid + 256];
  }
  if (tid==0){
    sh_np=0; sh_nv=0; sh_p0=0x7fffffff; sh_v0=0x7fffffff;
    sh_vl=-1; sh_v1=0x7fffffff; sh_li=0x7fffffff; sh_ri=-1;
  }
  __syncthreads();

  // ================= FFT: DIF radix 8,8,8,4 — no bit-reversal needed =================
  float ar[8], ai[8];
  float mx=-3.0e38f, mn=3.0e38f, sm=0.f, sq=0.f;

  // ---- pass 1: L=2048, r=8, t = tid; real inputs ----
  #pragma unroll
  for (int m=0;m<8;m++){
    float v = s_sig[tid + (m<<8)];
    ar[m]=v; ai[m]=0.f;
    mx=fmaxf(mx,v); mn=fminf(mn,v); sm+=v; sq+=v*v;
  }
  dft8(ar, ai);
  {
    float sn,cs; __sincosf(-2.f*PI_F*(float)tid*(1.f/2048.f), &sn, &cs);
    const int ob = tid + (tid>>5);          // padded base; q-offset = 264*q
    s_d[ob] = make_float2(ar[0], ai[0]);
    float wr=cs, wi=sn;
    #pragma unroll
    for (int q=1;q<8;q++){
      float rr,ii; cmul(ar[q],ai[q],wr,wi,rr,ii);
      s_d[ob + 264*q] = make_float2(rr,ii);
      float nr,ni; cmul(wr,wi,cs,sn,nr,ni); wr=nr; wi=ni;
    }
  }
  __syncthreads();

  // ---- pass 2: L=256, r=8; sub = warp, t = lane; offsets 33*m (disjoint per-thread set) ----
  {
    const int ob = warp*264 + lane;
    #pragma unroll
    for (int m=0;m<8;m++){ float2 v = s_d[ob + 33*m]; ar[m]=v.x; ai[m]=v.y; }
    dft8(ar, ai);
    float sn,cs; __sincosf(-2.f*PI_F*(float)lane*(1.f/256.f), &sn, &cs);
    float wr=cs, wi=sn;
    s_d[ob] = make_float2(ar[0], ai[0]);
    #pragma unroll
    for (int q=1;q<8;q++){
      float rr,ii; cmul(ar[q],ai[q],wr,wi,rr,ii);
      s_d[ob + 33*q] = make_float2(rr,ii);
      float nr,ni; cmul(wr,wi,cs,sn,nr,ni); wr=nr; wi=ni;
    }
  }
  __syncthreads();

  // ---- pass 3: L=32, r=8; t = tid>>6, sid = tid&63; offsets 4*m ----
  {
    const int t = tid>>6, sid = tid&63;
    const int ob = sid*33 + t;
    #pragma unroll
    for (int m=0;m<8;m++){ float2 v = s_d[ob + 4*m]; ar[m]=v.x; ai[m]=v.y; }
    dft8(ar, ai);
    float sn,cs; __sincosf(-2.f*PI_F*(float)t*(1.f/32.f), &sn, &cs);
    float wr=cs, wi=sn;
    s_d[ob] = make_float2(ar[0], ai[0]);
    #pragma unroll
    for (int q=1;q<8;q++){
      float rr,ii; cmul(ar[q],ai[q],wr,wi,rr,ii);
      s_d[ob + 4*q] = make_float2(rr,ii);
      float nr,ni; cmul(wr,wi,cs,sn,nr,ni); wr=nr; wi=ni;
    }
  }
  __syncthreads();

  // ---- pass 4: L=4, r=4, no twiddle; accumulate |X| directly ----
  float mag = 0.f;
  #pragma unroll
  for (int h=0; h<2; h++){
    int g  = tid + (h<<8);
    int o4 = (g<<2) + (g>>3);   // pad: (4g+j)>>5 == g>>3 for j<4
    float2 A=s_d[o4], B=s_d[o4+1], C=s_d[o4+2], D=s_d[o4+3];
    float u0r=A.x+C.x, u0i=A.y+C.y, u1r=A.x-C.x, u1i=A.y-C.y;
    float u2r=B.x+D.x, u2i=B.y+D.y, u3r=B.x-D.x, u3i=B.y-D.y;
    float y0r=u0r+u2r, y0i=u0i+u2i;
    float y2r=u0r-u2r, y2i=u0i-u2i;
    float y1r=u1r+u3i, y1i=u1i-u3r;
    float y3r=u1r-u3i, y3i=u1i+u3r;
    float n0=y0r*y0r+y0i*y0i, n1=y1r*y1r+y1i*y1i;
    float n2=y2r*y2r+y2i*y2i, n3=y3r*y3r+y3i*y3i;
    mag += n0*rsqrtf(fmaxf(n0,1e-30f)) + n1*rsqrtf(fmaxf(n1,1e-30f))
         + n2*rsqrtf(fmaxf(n2,1e-30f)) + n3*rsqrtf(fmaxf(n3,1e-30f));
  }

  // ---- fused deterministic reductions (5-way), valid on tid 0 ----
  #pragma unroll
  for (int o=16;o;o>>=1){
    sm  += __shfl_xor_sync(0xffffffffu, sm,  o);
    sq  += __shfl_xor_sync(0xffffffffu, sq,  o);
    mag += __shfl_xor_sync(0xffffffffu, mag, o);
    mx   = fmaxf(mx, __shfl_xor_sync(0xffffffffu, mx, o));
    mn   = fminf(mn, __shfl_xor_sync(0xffffffffu, mn, o));
  }
  if (lane==0){
    scr[warp]=sm; scr[8+warp]=sq; scr[16+warp]=mag; scr[24+warp]=mx; scr[32+warp]=mn;
  }
  __syncthreads();
  float sm_t=0.f, sq_t=0.f, mag_t=0.f, mx_t=-3.0e38f, mn_t=3.0e38f;
  if (tid==0){
    #pragma unroll
    for (int i=0;i<8;i++){
      sm_t+=scr[i]; sq_t+=scr[8+i]; mag_t+=scr[16+i];
      mx_t=fmaxf(mx_t,scr[24+i]); mn_t=fminf(mn_t,scr[32+i]);
    }
  }

  // ================= peak/valley features =================
  float sl[8], sc[8], srr[8];
  #pragma unroll
  for (int r=0;r<8;r++){
    sl[r]=0.f; sc[r]=0.f; srr[r]=0.f;
    int i = 1 + tid + (r<<8);
    if (i<=2047){ sl[r]=s_sig[i-1]; sc[r]=s_sig[i]; }
    if (i<=2046){ srr[r]=s_sig[i+1]; }
  }

  // Phase 1: counts, first peak, first/last valley
  {
    int lnp=0, lnv=0, lp0=0x7fffffff, lv0=0x7fffffff, lvl=-1;
    #pragma unroll
    for (int r=0;r<8;r++){
      int i = 1 + tid + (r<<8);
      if (i<=2046){
        bool pk = (sl[r]<sc[r]) && (sc[r]>srr[r]);
        bool vl = (sl[r]>sc[r]) && (sc[r]<srr[r]);
        if (pk){ lnp++; lp0 = min(lp0,i); }
        if (vl){ lnv++; lv0 = min(lv0,i); lvl = max(lvl,i); }
      }
    }
    if (lnp) atomicAdd(&sh_np, lnp);
    if (lnv) atomicAdd(&sh_nv, lnv);
    if (lp0!=0x7fffffff) atomicMin(&sh_p0, lp0);
    if (lv0!=0x7fffffff){ atomicMin(&sh_v0, lv0); atomicMax(&sh_vl, lvl); }
  }
  __syncthreads();

  const int np = sh_np, nv = sh_nv;
  const int p0 = (sh_p0==0x7fffffff) ? 1 : sh_p0;
  const int v0 = (sh_v0==0x7fffffff) ? 1 : sh_v0;
  const int vlast = (sh_vl<0) ? 2046 : sh_vl;
  const float half = 0.5f*(s_sig[p0] + s_sig[v0]);

  // Phase 2: second valley (>v0), half-height crossings
  {
    int lv1=0x7fffffff, lli=0x7fffffff, lri=-1;
    #pragma unroll
    for (int r=0;r<8;r++){
      int i = 1 + tid + (r<<8);
      if (i<=2046){
        bool vl = (sl[r]>sc[r]) && (sc[r]<srr[r]);
        if (vl && i>v0) lv1 = min(lv1,i);
        float sv = sc[r];
        if (sv>=half){
          if (i>=v0 && i< p0) lli = min(lli,i);
          if (i> v0 && i<=p0) lri = max(lri,i);
        }
      }
    }
    if (lv1!=0x7fffffff) atomicMin(&sh_v1, lv1);
    if (lli!=0x7fffffff) atomicMin(&sh_li, lli);
    if (lri>=0)          atomicMax(&sh_ri, lri);
  }
  __syncthreads();

  const int v1 = (sh_v1==0x7fffffff) ? 1  : sh_v1;
  const int li = (sh_li==0x7fffffff) ? v0 : sh_li;
  const int ri = (sh_ri<0)           ? p0 : sh_ri;

  // Phase 3: masked trapezoid sums
  float aPA=0.f, aA2=0.f, aA1=0.f;
  #pragma unroll
  for (int r=0;r<8;r++){
    int ip = tid + (r<<8);
    if (ip<=2046){
      float pr = 0.5f*(sl[r] + sc[r]);   // sl=s[ip], sc=s[ip+1]
      if (ip>=v0 && ip<=vlast-2) aPA += pr;
      if (ip>=p0 && ip<=v1-2)    aA2 += pr;
      if (ip>=v0 && ip<=p0-2)    aA1 += pr;
    }
  }
  #pragma unroll
  for (int o=16;o;o>>=1){
    aPA += __shfl_xor_sync(0xffffffffu, aPA, o);
    aA2 += __shfl_xor_sync(0xffffffffu, aA2, o);
    aA1 += __shfl_xor_sync(0xffffffffu, aA1, o);
  }
  if (lane==0){ scr[warp]=aPA; scr[8+warp]=aA2; scr[16+warp]=aA1; }
  __syncthreads();

  // ---- write 10 features ----
  if (tid==0){
    float PA_t=0.f, A2_t=0.f, A1_t=0.f;
    #pragma unroll
    for (int i=0;i<8;i++){ PA_t+=scr[i]; A2_t+=scr[8+i]; A1_t+=scr[16+i]; }
    const float n = 2048.f;
    float var = (sq_t - sm_t*sm_t/n) / (n - 1.f);
    var = fmaxf(var, 0.f);
    float stdv = sqrtf(var);
    float mean_amp = mag_t / n;
    bool gate = (np>=1) && (nv>=2);
    float PA=0.f, A2=0.f, PH=0.f, A1=0.f, PW=0.f;
    if (gate){
      PA = PA_t / 30.0f;
      A2 = A2_t / 30.0f;
      A1 = A1_t / 30.0f;
      PH = s_sig[p0] - s_sig[v0];
      PW = (float)(ri - li) / 30.0f;
    }
    float* o = out + row*10;
    o[0]=mx_t; o[1]=mx_t-mn_t; o[2]=var; o[3]=stdv; o[4]=mean_amp;
    o[5]=PA;   o[6]=A2;        o[7]=PH;  o[8]=A1;   o[9]=PW;
  }
}

extern "C" void kernel_launch(void* const* d_in, const int* in_sizes, int n_in,
                              void* d_out, int out_size) {
  const float* x = (const float*)d_in[0];
  float* out = (float*)d_out;
  (void)in_sizes; (void)n_in; (void)out_size;
  feat_kernel<<<32768, 256>>>(x, out);
}

// round 3
// speedup vs baseline: 1.5620x; 1.3558x over previous
#include <cuda_runtime.h>

#define PI_F 3.14159265358979323846f

static __device__ __forceinline__ void cmul(float ar,float ai,float br,float bi,float&cr,float&ci){
  cr = ar*br - ai*bi; ci = ar*bi + ai*br;
}

// DFT-8 (unscaled, e^{-2pi i mq/8}) on 8 complex values in registers.
static __device__ __forceinline__ void dft8(float xr[8], float xi[8]) {
  const float C = 0.70710678118654752440f;
  float u0r=xr[0]+xr[4], u0i=xi[0]+xi[4];
  float u1r=xr[0]-xr[4], u1i=xi[0]-xi[4];
  float u2r=xr[2]+xr[6], u2i=xi[2]+xi[6];
  float u3r=xr[2]-xr[6], u3i=xi[2]-xi[6];
  float E0r=u0r+u2r, E0i=u0i+u2i;
  float E1r=u1r+u3i, E1i=u1i-u3r;
  float E2r=u0r-u2r, E2i=u0i-u2i;
  float E3r=u1r-u3i, E3i=u1i+u3r;
  float v0r=xr[1]+xr[5], v0i=xi[1]+xi[5];
  float v1r=xr[1]-xr[5], v1i=xi[1]-xi[5];
  float v2r=xr[3]+xr[7], v2i=xi[3]+xi[7];
  float v3r=xr[3]-xr[7], v3i=xi[3]-xi[7];
  float O0r=v0r+v2r, O0i=v0i+v2i;
  float O1r=v1r+v3i, O1i=v1i-v3r;
  float O2r=v0r-v2r, O2i=v0i-v2i;
  float O3r=v1r-v3i, O3i=v1i+v3r;
  float w1r=C*(O1r+O1i), w1i=C*(O1i-O1r);
  float w2r=O2i,          w2i=-O2r;
  float w3r=C*(O3i-O3r),  w3i=-C*(O3r+O3i);
  xr[0]=E0r+O0r; xi[0]=E0i+O0i;
  xr[4]=E0r-O0r; xi[4]=E0i-O0i;
  xr[1]=E1r+w1r; xi[1]=E1i+w1i;
  xr[5]=E1r-w1r; xi[5]=E1i-w1i;
  xr[2]=E2r+w2r; xi[2]=E2i+w2i;
  xr[6]=E2r-w2r; xi[6]=E2i-w2i;
  xr[3]=E3r+w3r; xi[3]=E3i+w3i;
  xr[7]=E3r-w3r; xi[7]=E3i-w3i;
}

// position of frequency k (0..1023) in DIF radix-(8,8,8,2) output order
static __device__ __forceinline__ int posf(int k){
  return ((k&7)<<7) | (((k>>3)&7)<<4) | (((k>>6)&7)<<1) | (k>>9);
}

__global__ void __launch_bounds__(128)
feat_kernel(const float* __restrict__ x, float* __restrict__ out)
{
  __shared__ float  s_sig[2048];
  __shared__ float2 s_d[1056];   // 1024 complex + pad (i -> i + (i>>5))
  __shared__ float  scr[20];
  __shared__ int sh_np, sh_nv, sh_p0, sh_v0, sh_vl, sh_v1, sh_li, sh_ri;

  const int tid  = threadIdx.x;   // 0..127
  const int lane = tid & 31;
  const int warp = tid >> 5;      // 0..3
  const size_t row = blockIdx.x;
  const float* xp = x + row * 2048;

  // ---- load row (coalesced float4, 4 per thread) ----
  {
    const float4* xv = (const float4*)xp;
    float4* sv = (float4*)s_sig;
    #pragma unroll
    for (int c=0;c<4;c++) sv[tid + (c<<7)] = xv[tid + (c<<7)];
  }
  if (tid==0){
    sh_np=0; sh_nv=0; sh_p0=0x7fffffff; sh_v0=0x7fffffff;
    sh_vl=-1; sh_v1=0x7fffffff; sh_li=0x7fffffff; sh_ri=-1;
  }
  __syncthreads();

  // ============ 1024-pt complex FFT of z_n = x[2n] + i x[2n+1], DIF 8,8,8,2 ============
  float ar[8], ai[8];
  float mx=-3.0e38f, mn=3.0e38f, sm=0.f, sq=0.f;

  // ---- pass 1: L=1024, stride 128, t = tid ----
  {
    const float2* zin = (const float2*)s_sig;
    #pragma unroll
    for (int m=0;m<8;m++){
      float2 z = zin[tid + (m<<7)];
      ar[m]=z.x; ai[m]=z.y;
      mx=fmaxf(mx,fmaxf(z.x,z.y)); mn=fminf(mn,fminf(z.x,z.y));
      sm += z.x + z.y; sq += z.x*z.x + z.y*z.y;
    }
    dft8(ar, ai);
    float sn,cs; __sincosf(-2.f*PI_F*(float)tid*(1.f/1024.f), &sn, &cs);
    const int ob = tid + (tid>>5);   // q offset = 132
    s_d[ob] = make_float2(ar[0], ai[0]);
    float wr=cs, wi=sn;
    #pragma unroll
    for (int q=1;q<8;q++){
      float rr,ii; cmul(ar[q],ai[q],wr,wi,rr,ii);
      s_d[ob + 132*q] = make_float2(rr,ii);
      float nr,ni; cmul(wr,wi,cs,sn,nr,ni); wr=nr; wi=ni;
    }
  }
  __syncthreads();

  // ---- pass 2: L=128, stride 16; sub = tid>>4, tt = tid&15 ----
  {
    const int sub = tid>>4, tt = tid&15;
    const int ob = 132*sub + tt;    // m offset = 16m + (m>>1)
    #pragma unroll
    for (int m=0;m<8;m++){ float2 v = s_d[ob + 16*m + (m>>1)]; ar[m]=v.x; ai[m]=v.y; }
    dft8(ar, ai);
    float sn,cs; __sincosf(-2.f*PI_F*(float)tt*(1.f/128.f), &sn, &cs);
    float wr=cs, wi=sn;
    s_d[ob] = make_float2(ar[0], ai[0]);
    #pragma unroll
    for (int q=1;q<8;q++){
      float rr,ii; cmul(ar[q],ai[q],wr,wi,rr,ii);
      s_d[ob + 16*q + (q>>1)] = make_float2(rr,ii);
      float nr,ni; cmul(wr,wi,cs,sn,nr,ni); wr=nr; wi=ni;
    }
  }
  __syncthreads();

  // ---- pass 3: L=16, stride 2; tt = tid>>6 (0/1), sid = tid&63 ----
  {
    const int tt = tid>>6, sid = tid&63;
    const int ob = 16*sid + (sid>>1) + tt;   // m offset = 2m (tt+2m <= 15, no pad step)
    #pragma unroll
    for (int m=0;m<8;m++){ float2 v = s_d[ob + 2*m]; ar[m]=v.x; ai[m]=v.y; }
    dft8(ar, ai);
    float sn,cs; __sincosf(-2.f*PI_F*(float)tt*(1.f/16.f), &sn, &cs);
    float wr=cs, wi=sn;
    s_d[ob] = make_float2(ar[0], ai[0]);
    #pragma unroll
    for (int q=1;q<8;q++){
      float rr,ii; cmul(ar[q],ai[q],wr,wi,rr,ii);
      s_d[ob + 2*q] = make_float2(rr,ii);
      float nr,ni; cmul(wr,wi,cs,sn,nr,ni); wr=nr; wi=ni;
    }
  }
  __syncthreads();

  // ---- pass 4: radix-2 pairs (2j, 2j+1), j = tid + 128c ----
  #pragma unroll
  for (int c=0;c<4;c++){
    int j = tid + (c<<7);
    int o = 2*j + (j>>4);
    float2 a = s_d[o], b = s_d[o+1];
    s_d[o]   = make_float2(a.x+b.x, a.y+b.y);
    s_d[o+1] = make_float2(a.x-b.x, a.y-b.y);
  }
  __syncthreads();

  // ---- unpack real-FFT magnitudes: slots k = 1 + tid + 128c ----
  float mag = 0.f;
  {
    const float W128r =  0.92387953251128675613f;  // cos(-pi/8)
    const float W128i = -0.38268343236508977173f;  // sin(-pi/8)
    int k0 = 1 + tid;
    float wr, wi; __sincosf(-PI_F*(float)k0*(1.f/1024.f), &wi, &wr);
    #pragma unroll
    for (int c=0;c<4;c++){
      int k  = k0 + (c<<7);
      int k2 = 1024 - k;
      int p1 = posf(k),  p2 = posf(k2);
      float2 Z1 = s_d[p1 + (p1>>5)];
      float2 Z2 = s_d[p2 + (p2>>5)];
      float Er = 0.5f*(Z1.x + Z2.x);
      float Ei = 0.5f*(Z1.y - Z2.y);
      float Or = 0.5f*(Z1.y + Z2.y);
      float Oi = 0.5f*(Z2.x - Z1.x);
      float Tr = wr*Or - wi*Oi;
      float Ti = wr*Oi + wi*Or;
      float n1 = (Er+Tr)*(Er+Tr) + (Ei+Ti)*(Ei+Ti);
      float n2 = (Er-Tr)*(Er-Tr) + (Ei-Ti)*(Ei-Ti);
      float m1 = n1*rsqrtf(fmaxf(n1,1e-30f));
      float m2 = n2*rsqrtf(fmaxf(n2,1e-30f));
      float sc = (k==512) ? 0.5f : 1.0f;   // k=512 pair degenerates (counts itself twice)
      mag += sc*(m1+m2);
      float nr,ni; cmul(wr,wi,W128r,W128i,nr,ni); wr=nr; wi=ni;
    }
    if (tid==0){
      float2 Z0 = s_d[0];
      mag += 0.5f*(fabsf(Z0.x+Z0.y) + fabsf(Z0.x-Z0.y));  // (|X0|+|X1024|)/2
    }
  }

  // ---- fused deterministic reductions (5-way), valid on tid 0 ----
  #pragma unroll
  for (int o=16;o;o>>=1){
    sm  += __shfl_xor_sync(0xffffffffu, sm,  o);
    sq  += __shfl_xor_sync(0xffffffffu, sq,  o);
    mag += __shfl_xor_sync(0xffffffffu, mag, o);
    mx   = fmaxf(mx, __shfl_xor_sync(0xffffffffu, mx, o));
    mn   = fminf(mn, __shfl_xor_sync(0xffffffffu, mn, o));
  }
  if (lane==0){
    scr[warp]=sm; scr[4+warp]=sq; scr[8+warp]=mag; scr[12+warp]=mx; scr[16+warp]=mn;
  }
  __syncthreads();
  float sm_t=0.f, sq_t=0.f, mag_t=0.f, mx_t=-3.0e38f, mn_t=3.0e38f;
  if (tid==0){
    #pragma unroll
    for (int i=0;i<4;i++){
      sm_t+=scr[i]; sq_t+=scr[4+i]; mag_t+=scr[8+i];
      mx_t=fmaxf(mx_t,scr[12+i]); mn_t=fminf(mn_t,scr[16+i]);
    }
  }

  // ================= peak/valley: contiguous 16-wide chunk per thread =================
  const int base = tid<<4;          // covers s[base .. base+17]
  float v[18];
  #pragma unroll
  for (int c=0;c<4;c++){
    float4 q = *(const float4*)&s_sig[base + (c<<2)];
    v[4*c]=q.x; v[4*c+1]=q.y; v[4*c+2]=q.z; v[4*c+3]=q.w;
  }
  v[16] = (base+16 < 2048) ? s_sig[base+16] : 0.f;
  v[17] = (base+17 < 2048) ? s_sig[base+17] : 0.f;

  // Phase 1: counts, first peak, first/last valley; build masks
  unsigned pmask=0u, vmask=0u;
  {
    int lnp=0, lnv=0, lp0=0x7fffffff, lv0=0x7fffffff, lvl=-1;
    #pragma unroll
    for (int j=0;j<16;j++){
      int i = base + j + 1;
      if (i<=2046){
        bool pk = (v[j]<v[j+1]) && (v[j+1]>v[j+2]);
        bool vl = (v[j]>v[j+1]) && (v[j+1]<v[j+2]);
        if (pk){ lnp++; pmask |= (1u<<j); lp0 = min(lp0,i); }
        if (vl){ lnv++; vmask |= (1u<<j); lv0 = min(lv0,i); lvl = max(lvl,i); }
      }
    }
    if (lnp) atomicAdd(&sh_np, lnp);
    if (lnv) atomicAdd(&sh_nv, lnv);
    if (lp0!=0x7fffffff) atomicMin(&sh_p0, lp0);
    if (lv0!=0x7fffffff){ atomicMin(&sh_v0, lv0); atomicMax(&sh_vl, lvl); }
  }
  __syncthreads();

  const int np = sh_np, nv = sh_nv;
  const int p0 = (sh_p0==0x7fffffff) ? 1 : sh_p0;
  const int v0 = (sh_v0==0x7fffffff) ? 1 : sh_v0;
  const int vlast = (sh_vl<0) ? 2046 : sh_vl;
  const float half = 0.5f*(s_sig[p0] + s_sig[v0]);

  // Phase 2: second valley (>v0), half-height crossings
  {
    int lv1=0x7fffffff, lli=0x7fffffff, lri=-1;
    #pragma unroll
    for (int j=0;j<16;j++){
      int i = base + j + 1;
      if ((vmask>>j)&1u){ if (i>v0) lv1 = min(lv1,i); }
      if (v[j+1]>=half){
        if (i>=v0 && i< p0) lli = min(lli,i);
        if (i> v0 && i<=p0) lri = max(lri,i);
      }
    }
    if (lv1!=0x7fffffff) atomicMin(&sh_v1, lv1);
    if (lli!=0x7fffffff) atomicMin(&sh_li, lli);
    if (lri>=0)          atomicMax(&sh_ri, lri);
  }
  __syncthreads();

  const int v1 = (sh_v1==0x7fffffff) ? 1  : sh_v1;
  const int li = (sh_li==0x7fffffff) ? v0 : sh_li;
  const int ri = (sh_ri<0)           ? p0 : sh_ri;

  // Phase 3: masked trapezoid sums; pair ip = base+j, pr = 0.5*(v[j]+v[j+1])
  float aPA=0.f, aA2=0.f, aA1=0.f;
  #pragma unroll
  for (int j=0;j<16;j++){
    int ip = base + j;
    if (ip<=2046){
      float pr = 0.5f*(v[j] + v[j+1]);
      if (ip>=v0 && ip<=vlast-2) aPA += pr;
      if (ip>=p0 && ip<=v1-2)    aA2 += pr;
      if (ip>=v0 && ip<=p0-2)    aA1 += pr;
    }
  }
  #pragma unroll
  for (int o=16;o;o>>=1){
    aPA += __shfl_xor_sync(0xffffffffu, aPA, o);
    aA2 += __shfl_xor_sync(0xffffffffu, aA2, o);
    aA1 += __shfl_xor_sync(0xffffffffu, aA1, o);
  }
  if (lane==0){ scr[warp]=aPA; scr[4+warp]=aA2; scr[8+warp]=aA1; }
  __syncthreads();

  // ---- write 10 features ----
  if (tid==0){
    float PA_t=0.f, A2_t=0.f, A1_t=0.f;
    #pragma unroll
    for (int i=0;i<4;i++){ PA_t+=scr[i]; A2_t+=scr[4+i]; A1_t+=scr[8+i]; }
    const float n = 2048.f;
    float var = (sq_t - sm_t*sm_t/n) / (n - 1.f);
    var = fmaxf(var, 0.f);
    float stdv = sqrtf(var);
    float mean_amp = (2.f*mag_t) / n;   // pairs counted once; total = 2*mag
    bool gate = (np>=1) && (nv>=2);
    float PA=0.f, A2=0.f, PH=0.f, A1=0.f, PW=0.f;
    if (gate){
      PA = PA_t / 30.0f;
      A2 = A2_t / 30.0f;
      A1 = A1_t / 30.0f;
      PH = s_sig[p0] - s_sig[v0];
      PW = (float)(ri - li) / 30.0f;
    }
    float* o = out + row*10;
    o[0]=mx_t; o[1]=mx_t-mn_t; o[2]=var; o[3]=stdv; o[4]=mean_amp;
    o[5]=PA;   o[6]=A2;        o[7]=PH;  o[8]=A1;   o[9]=PW;
  }
}

extern "C" void kernel_launch(void* const* d_in, const int* in_sizes, int n_in,
                              void* d_out, int out_size) {
  const float* x = (const float*)d_in[0];
  float* out = (float*)d_out;
  (void)in_sizes; (void)n_in; (void)out_size;
  feat_kernel<<<32768, 128>>>(x, out);
}